// round 15
// baseline (speedup 1.0000x reference)
#include <cuda_runtime.h>
#include <math.h>
#include <string.h>

#define MAXE 48

// ---------------- device-global scratch (weight/wpath-dependent only) ----------------
__device__ float g_w1[768];          // pre-contracted W3@Wt1 : [p][l][128]
__device__ float g_w2[768];          // pre-contracted W3@Wt2
__device__ float g_c1, g_c2;         // bias scalars for (p=0, lm=0)
__device__ float g_lval[9 * MAXE];   // CG * wpath, per-c sparse lists
__device__ unsigned g_tile;          // work-stealing counter (reset each launch in k_prep)

// ---------------- host-computed constants passed by value (constant bank) ----------------
struct PrepConst {
    float         cgv[9 * MAXE];     // CG value per sparse entry (0 in unused slots)
    unsigned char wpidx[9 * MAXE];   // wpath flat index per sparse entry
};
struct MainConst {
    float         cgos[81];          // CG[1+i][1+j][c] laid out [k=i*3+j][c]
    int           lcnt[9];           // sparse-list counts per output c
    unsigned char lab[9 * MAXE];     // packed (a<<4)|b per sparse entry
};

// ================= HOST: Clebsch-Gordan construction (double precision) =================
static inline int h_lof(int i) { return i >= 4 ? 2 : (i >= 1 ? 1 : 0); }

static double h_dfact(int n) {
    static const double F[8] = {1., 1., 2., 6., 24., 120., 720., 5040.};
    return F[n];
}

static double h_cg_complex(int j1, int m1, int j2, int m2, int j3, int m3) {
    if (m3 != m1 + m2) return 0.0;
    int lo = j1 - j2; if (lo < 0) lo = -lo;
    if (j3 < lo || j3 > j1 + j2) return 0.0;
    double pref = sqrt((2.0 * j3 + 1.0) * h_dfact(j1 + j2 - j3) * h_dfact(j1 - j2 + j3) *
                       h_dfact(-j1 + j2 + j3) / h_dfact(j1 + j2 + j3 + 1));
    pref *= sqrt(h_dfact(j1 + m1) * h_dfact(j1 - m1) * h_dfact(j2 + m2) * h_dfact(j2 - m2) *
                 h_dfact(j3 + m3) * h_dfact(j3 - m3));
    double s = 0.0;
    for (int k = 0; k <= j1 + j2 - j3; k++) {
        int t1 = j1 + j2 - j3 - k, t2 = j1 - m1 - k, t3 = j2 + m2 - k;
        int t4 = j3 - j2 + m1 + k, t5 = j3 - j1 - m2 + k;
        if (t1 < 0 || t2 < 0 || t3 < 0 || t4 < 0 || t5 < 0) continue;
        double d = h_dfact(k) * h_dfact(t1) * h_dfact(t2) * h_dfact(t3) * h_dfact(t4) * h_dfact(t5);
        s += ((k & 1) ? -1.0 : 1.0) / d;
    }
    return pref * s;
}

static void h_umat_entry(int l, int r, int c, double* re, double* im) {
    *re = 0.0; *im = 0.0;
    int mr = r - l, mc = c - l;
    const double inv = 0.70710678118654752440;
    if (mr == 0) { if (mc == 0) *re = 1.0; return; }
    if (mr > 0) {
        int m = mr; double sgn = (m & 1) ? -1.0 : 1.0;
        if (mc == -m) *re = inv;
        else if (mc == m) *re = sgn * inv;
    } else {
        int m = -mr; double sgn = (m & 1) ? -1.0 : 1.0;
        if (mc == -m) *im = inv;
        else if (mc == m) *im = -sgn * inv;
    }
}

static void h_build_cg(float* cg /*729*/) {
    for (int t = 0; t < 729; t++) {
        int a = t / 81, b = (t / 9) % 9, c = t % 9;
        int l1 = h_lof(a), l2 = h_lof(b), l3 = h_lof(c);
        double re = 0.0, im = 0.0;
        int lo = l1 - l2; if (lo < 0) lo = -lo;
        if (l3 >= lo && l3 <= l1 + l2) {
            int aa = a - l1 * l1, bb = b - l2 * l2, cc = c - l3 * l3;
            for (int m = 0; m < 2 * l1 + 1; m++) {
                double u1r, u1i; h_umat_entry(l1, aa, m, &u1r, &u1i); u1i = -u1i;
                if (u1r == 0.0 && u1i == 0.0) continue;
                for (int nn = 0; nn < 2 * l2 + 1; nn++) {
                    double u2r, u2i; h_umat_entry(l2, bb, nn, &u2r, &u2i); u2i = -u2i;
                    if (u2r == 0.0 && u2i == 0.0) continue;
                    double pr = u1r * u2r - u1i * u2i;
                    double pi = u1r * u2i + u1i * u2r;
                    for (int o = 0; o < 2 * l3 + 1; o++) {
                        double u3r, u3i; h_umat_entry(l3, cc, o, &u3r, &u3i);
                        if (u3r == 0.0 && u3i == 0.0) continue;
                        double C = h_cg_complex(l1, m - l1, l2, nn - l2, l3, o - l3);
                        if (C == 0.0) continue;
                        re += (pr * u3r - pi * u3i) * C;
                        im += (pr * u3i + pi * u3r) * C;
                    }
                }
            }
        }
        double val = ((l1 + l2 + l3) & 1) ? im : re;
        cg[t] = (float)val;
    }
}

// ================= DEVICE: prelude — warp-per-output dot products (~1.5us) =================
__device__ __forceinline__ float dot4(float4 v, float4 w) {
    return fmaf(v.x, w.x, fmaf(v.y, w.y, fmaf(v.z, w.z, v.w * w.w)));
}

__global__ void k_prep(const float* __restrict__ W3, const float* __restrict__ b3,
                       const float* __restrict__ Wt1, const float* __restrict__ bt1,
                       const float* __restrict__ Wt2, const float* __restrict__ bt2,
                       const float* __restrict__ wpath, PrepConst pc) {
    int tid = threadIdx.x;
    int warp = tid >> 5, lane = tid & 31;

    if (blockIdx.x < 96) {
        if (blockIdx.x == 0 && tid == 0) g_tile = 0;   // reset work-stealing counter
        int t = blockIdx.x * 8 + warp;
        int pl = t >> 7;
        const float4* w3r = reinterpret_cast<const float4*>(W3) + (size_t)t * 32;
        const float4* v1r = reinterpret_cast<const float4*>(Wt1) + pl * 32;
        const float4* v2r = reinterpret_cast<const float4*>(Wt2) + pl * 32;
        float4 w = w3r[lane];
        float a1 = dot4(w, v1r[lane]);
        float a2 = dot4(w, v2r[lane]);
        #pragma unroll
        for (int d = 16; d > 0; d >>= 1) {
            a1 += __shfl_xor_sync(0xffffffffu, a1, d);
            a2 += __shfl_xor_sync(0xffffffffu, a2, d);
        }
        if (lane == 0) { g_w1[t] = a1; g_w2[t] = a2; }
    } else {
        if (warp == 0) {
            const float4* br  = reinterpret_cast<const float4*>(b3);
            const float4* v1r = reinterpret_cast<const float4*>(Wt1);
            const float4* v2r = reinterpret_cast<const float4*>(Wt2);
            float4 b = br[lane];
            float a1 = dot4(b, v1r[lane]);
            float a2 = dot4(b, v2r[lane]);
            #pragma unroll
            for (int d = 16; d > 0; d >>= 1) {
                a1 += __shfl_xor_sync(0xffffffffu, a1, d);
                a2 += __shfl_xor_sync(0xffffffffu, a2, d);
            }
            if (lane == 0) { g_c1 = a1 + bt1[0]; g_c2 = a2 + bt2[0]; }
        } else {
            for (int i = tid - 32; i < 9 * MAXE; i += 224)
                g_lval[i] = pc.cgv[i] * wpath[pc.wpidx[i]];
        }
    }
}

// ================= DEVICE: main streaming kernel — cp.async warp pipeline =================
// One block/SM (smem-bound). Each warp independently steals one n at a time, keeps a
// private double buffer (2 x 9216B) filled via cp.async.cg (no register cost), and
// computes from smem: lanes 0-15 accumulate x1 dots (w1), lanes 16-31 x2 dots (w2).

__device__ __forceinline__ unsigned smem_u32(const void* p) {
    unsigned u;
    asm("{ .reg .u64 t; cvta.to.shared.u64 t, %1; cvt.u32.u64 %0, t; }" : "=r"(u) : "l"(p));
    return u;
}

__device__ __forceinline__ void cp16(unsigned dst, const void* src) {
    asm volatile("cp.async.cg.shared.global [%0], [%1], 16;" :: "r"(dst), "l"(src));
}
#define CP_COMMIT() asm volatile("cp.async.commit_group;" ::: "memory")
#define CP_WAIT1()  asm volatile("cp.async.wait_group 1;" ::: "memory")

__device__ __forceinline__ unsigned warp_grab() {
    unsigned t = 0;
    if ((threadIdx.x & 31) == 0) t = atomicAdd(&g_tile, 1u);
    return __shfl_sync(0xffffffffu, t, 0);
}

__global__ void __launch_bounds__(256, 1)
k_main(const float* __restrict__ sf, float* __restrict__ out, int N, MainConst mc) {
    extern __shared__ char smem_raw[];
    float* data   = (float*)smem_raw;                 // 8 warps * 2 bufs * 2304 floats
    float* w1s    = data + 8 * 4608;                  // 768
    float* w2s    = w1s + 768;                        // 768
    float* lval_s = w2s + 768;                        // 432
    float* cgos   = lval_s + 9 * MAXE;                // 81
    float* xbufs  = cgos + 81;                        // 8 * 36
    float* tpbufs = xbufs + 8 * 36;                   // 8 * 9
    int*   lcnt_s = (int*)(tpbufs + 8 * 9);           // 9
    unsigned char* lab_s = (unsigned char*)(lcnt_s + 9);  // 432

    int tid = threadIdx.x;
    for (int i = tid; i < 768; i += 256) { w1s[i] = g_w1[i]; w2s[i] = g_w2[i]; }
    for (int i = tid; i < 9 * MAXE; i += 256) { lval_s[i] = g_lval[i]; lab_s[i] = mc.lab[i]; }
    if (tid < 81) cgos[tid] = mc.cgos[tid];
    if (tid < 9)  lcnt_s[tid] = mc.lcnt[tid];
    float c1 = g_c1, c2 = g_c2;
    __syncthreads();

    int warp = tid >> 5, lane = tid & 31;
    int h = lane >> 4;                  // 0: x1/w1 half, 1: x2/w2 half
    int q = lane & 15;                  // column pair {q, q+16}

    float* buf0 = data + warp * 4608;           // parity-0 buffer (2304 floats)
    float* buf1 = buf0 + 2304;                  // parity-1 buffer
    unsigned d0 = smem_u32(buf0) + lane * 16;
    unsigned d1 = smem_u32(buf1) + lane * 16;
    const char* sfc = (const char*)sf;

    float* xbuf  = xbufs  + warp * 36;
    float* tpbuf = tpbufs + warp * 9;

    unsigned uN = (unsigned)N;

    // ---- pipeline prologue: grab 2 n's, start both loads ----
    unsigned n0 = warp_grab();
    if (n0 < uN) {
        const char* src = sfc + (size_t)n0 * 9216 + lane * 16;
        #pragma unroll
        for (int k = 0; k < 18; k++) cp16(d0 + k * 512, src + k * 512);
    }
    CP_COMMIT();
    unsigned n1 = warp_grab();
    if (n1 < uN) {
        const char* src = sfc + (size_t)n1 * 9216 + lane * 16;
        #pragma unroll
        for (int k = 0; k < 18; k++) cp16(d1 + k * 512, src + k * 512);
    }
    CP_COMMIT();

    int pb = 0;
    while (n0 < uN) {
        unsigned n2 = warp_grab();              // steal next-next (latency hidden)

        CP_WAIT1();                             // n0's data resident
        __syncwarp();

        float* buf = pb ? buf1 : buf0;
        const float* ws = h ? w2s : w1s;

        // ---- 18 per-row partial dots over columns {q, q+16} ----
        float s[18];
        {
            int r = 0;
            #pragma unroll
            for (int p = 0; p < 2; p++) {
                #pragma unroll
                for (int l = 0; l < 3; l++) {
                    const float4* wp = reinterpret_cast<const float4*>(ws) + (p * 3 + l) * 32;
                    float4 a0 = wp[q], a1 = wp[q + 16];
                    const int nlm = 2 * l + 1;
                    #pragma unroll
                    for (int j = 0; j < nlm; j++) {
                        const float4* rp = reinterpret_cast<const float4*>(buf) + (p * 9 + l * l + j) * 32;
                        s[r] = dot4(rp[q], a0) + dot4(rp[q + 16], a1);
                        r++;
                    }
                }
            }
        }
        // ---- width-16 butterfly within each half-warp ----
        #pragma unroll
        for (int r = 0; r < 18; r++) {
            s[r] += __shfl_xor_sync(0xffffffffu, s[r], 1);
            s[r] += __shfl_xor_sync(0xffffffffu, s[r], 2);
            s[r] += __shfl_xor_sync(0xffffffffu, s[r], 4);
            s[r] += __shfl_xor_sync(0xffffffffu, s[r], 8);
        }
        s[0] += h ? c2 : c1;                    // bias on even-parity scalar channel

        if (q == 0) {                           // lane 0 -> x1, lane 16 -> x2
            #pragma unroll
            for (int r = 0; r < 18; r++) xbuf[h * 18 + r] = s[r];
        }
        __syncwarp();

        // ---- sparse tensor product tp[c] (lanes 0-8) ----
        if (lane < 9) {
            int c = lane;
            float tp = 0.f;
            int cnt = lcnt_s[c];
            const unsigned char* pab = lab_s + c * MAXE;
            const float*         pv  = lval_s + c * MAXE;
            for (int e = 0; e < cnt; e++) {
                int ab = pab[e];
                float val = pv[e];
                int a = ab >> 4, b = ab & 15;
                float t0 = xbuf[a] * xbuf[18 + b];
                float t1 = fmaf(xbuf[9 + a], xbuf[27 + b], t0);
                tp = fmaf(val, t1, tp);
            }
            tpbuf[c] = tp;
        }
        __syncwarp();

        // ---- out[i,j] = sum_c tp[c] * CG[1+i,1+j,c] (lanes 0-8) ----
        if (lane < 9) {
            int k = lane;
            float o = 0.f;
            #pragma unroll
            for (int c = 0; c < 9; c++) o = fmaf(tpbuf[c], cgos[k * 9 + c], o);
            out[(size_t)n0 * 9 + k] = o;
        }
        __syncwarp();                           // all lanes done with buf before refill

        // ---- refill consumed buffer with n2 ----
        if (n2 < uN) {
            const char* src = sfc + (size_t)n2 * 9216 + lane * 16;
            unsigned dst = pb ? d1 : d0;
            #pragma unroll
            for (int k = 0; k < 18; k++) cp16(dst + k * 512, src + k * 512);
        }
        CP_COMMIT();

        n0 = n1; n1 = n2; pb ^= 1;
    }
}

// ================= launch =================
extern "C" void kernel_launch(void* const* d_in, const int* in_sizes, int n_in,
                              void* d_out, int out_size) {
    const float* sf    = (const float*)d_in[0];
    const float* W3    = (const float*)d_in[1];
    const float* b3    = (const float*)d_in[2];
    const float* Wt1   = (const float*)d_in[3];
    const float* bt1   = (const float*)d_in[4];
    const float* Wt2   = (const float*)d_in[5];
    const float* bt2   = (const float*)d_in[6];
    const float* wpath = (const float*)d_in[7];

    int N = in_sizes[0] / 2304;  // N * 2 * 9 * 128

    // ---- host-side constant construction (pure CPU, graph-safe) ----
    float cg[729];
    h_build_cg(cg);

    PrepConst pc;
    MainConst mcst;
    memset(&pc, 0, sizeof(pc));
    memset(&mcst, 0, sizeof(mcst));

    for (int t = 0; t < 81; t++) {
        int k = t / 9, c = t % 9;
        int ii = k / 3, jj = k % 3;
        mcst.cgos[t] = cg[(1 + ii) * 81 + (1 + jj) * 9 + c];
    }
    for (int c = 0; c < 9; c++) {
        int cnt = 0;
        for (int ab = 0; ab < 81; ab++) {
            int idx = ab * 9 + c;
            if (fabsf(cg[idx]) > 1e-6f && cnt < MAXE) {
                int a = ab / 9, b = ab % 9;
                mcst.lab[c * MAXE + cnt] = (unsigned char)((a << 4) | b);
                pc.cgv[c * MAXE + cnt]   = cg[idx];
                pc.wpidx[c * MAXE + cnt] = (unsigned char)((h_lof(a) * 3 + h_lof(b)) * 3 + h_lof(c));
                cnt++;
            }
        }
        mcst.lcnt[c] = cnt;
    }

    // dynamic smem: 8*4608 + 768 + 768 + 432 + 81 + 288 + 72 floats + lcnt/lab bytes
    const int SMEM_BYTES = (8 * 4608 + 768 + 768 + 9 * MAXE + 81 + 8 * 36 + 8 * 9) * 4
                           + 9 * 4 + 9 * MAXE + 128;
    static int smem_set = 0;
    if (!smem_set) {
        cudaFuncSetAttribute(k_main, cudaFuncAttributeMaxDynamicSharedMemorySize, SMEM_BYTES);
        smem_set = 1;
    }

    // ---- device work: parallel prelude (+counter reset) + warp-pipelined streaming ----
    k_prep<<<97, 256>>>(W3, b3, Wt1, bt1, Wt2, bt2, wpath, pc);
    k_main<<<160, 256, SMEM_BYTES>>>(sf, (float*)d_out, N, mcst);
}

// round 16
// speedup vs baseline: 1.0043x; 1.0043x over previous
#include <cuda_runtime.h>
#include <math.h>
#include <string.h>

#define MAXE 48

// ---------------- device-global scratch (weight/wpath-dependent only) ----------------
__device__ float g_w1[768];          // pre-contracted W3@Wt1 : [p][l][128]
__device__ float g_w2[768];          // pre-contracted W3@Wt2
__device__ float g_c1, g_c2;         // bias scalars for (p=0, lm=0)
__device__ float g_lval[9 * MAXE];   // CG * wpath, per-c sparse lists
__device__ unsigned g_tile;          // work-stealing counter (reset each launch in k_prep)

// ---------------- host-computed constants passed by value (constant bank) ----------------
struct PrepConst {
    float         cgv[9 * MAXE];     // CG value per sparse entry (0 in unused slots)
    unsigned char wpidx[9 * MAXE];   // wpath flat index per sparse entry
};
struct MainConst {
    float         cgos[81];          // CG[1+i][1+j][c] laid out [k=i*3+j][c]
    int           lcnt[9];           // sparse-list counts per output c
    unsigned char lab[9 * MAXE];     // packed (a<<4)|b per sparse entry
};

// ================= HOST: Clebsch-Gordan construction (double precision) =================
static inline int h_lof(int i) { return i >= 4 ? 2 : (i >= 1 ? 1 : 0); }

static double h_dfact(int n) {
    static const double F[8] = {1., 1., 2., 6., 24., 120., 720., 5040.};
    return F[n];
}

static double h_cg_complex(int j1, int m1, int j2, int m2, int j3, int m3) {
    if (m3 != m1 + m2) return 0.0;
    int lo = j1 - j2; if (lo < 0) lo = -lo;
    if (j3 < lo || j3 > j1 + j2) return 0.0;
    double pref = sqrt((2.0 * j3 + 1.0) * h_dfact(j1 + j2 - j3) * h_dfact(j1 - j2 + j3) *
                       h_dfact(-j1 + j2 + j3) / h_dfact(j1 + j2 + j3 + 1));
    pref *= sqrt(h_dfact(j1 + m1) * h_dfact(j1 - m1) * h_dfact(j2 + m2) * h_dfact(j2 - m2) *
                 h_dfact(j3 + m3) * h_dfact(j3 - m3));
    double s = 0.0;
    for (int k = 0; k <= j1 + j2 - j3; k++) {
        int t1 = j1 + j2 - j3 - k, t2 = j1 - m1 - k, t3 = j2 + m2 - k;
        int t4 = j3 - j2 + m1 + k, t5 = j3 - j1 - m2 + k;
        if (t1 < 0 || t2 < 0 || t3 < 0 || t4 < 0 || t5 < 0) continue;
        double d = h_dfact(k) * h_dfact(t1) * h_dfact(t2) * h_dfact(t3) * h_dfact(t4) * h_dfact(t5);
        s += ((k & 1) ? -1.0 : 1.0) / d;
    }
    return pref * s;
}

static void h_umat_entry(int l, int r, int c, double* re, double* im) {
    *re = 0.0; *im = 0.0;
    int mr = r - l, mc = c - l;
    const double inv = 0.70710678118654752440;
    if (mr == 0) { if (mc == 0) *re = 1.0; return; }
    if (mr > 0) {
        int m = mr; double sgn = (m & 1) ? -1.0 : 1.0;
        if (mc == -m) *re = inv;
        else if (mc == m) *re = sgn * inv;
    } else {
        int m = -mr; double sgn = (m & 1) ? -1.0 : 1.0;
        if (mc == -m) *im = inv;
        else if (mc == m) *im = -sgn * inv;
    }
}

static void h_build_cg(float* cg /*729*/) {
    for (int t = 0; t < 729; t++) {
        int a = t / 81, b = (t / 9) % 9, c = t % 9;
        int l1 = h_lof(a), l2 = h_lof(b), l3 = h_lof(c);
        double re = 0.0, im = 0.0;
        int lo = l1 - l2; if (lo < 0) lo = -lo;
        if (l3 >= lo && l3 <= l1 + l2) {
            int aa = a - l1 * l1, bb = b - l2 * l2, cc = c - l3 * l3;
            for (int m = 0; m < 2 * l1 + 1; m++) {
                double u1r, u1i; h_umat_entry(l1, aa, m, &u1r, &u1i); u1i = -u1i;
                if (u1r == 0.0 && u1i == 0.0) continue;
                for (int nn = 0; nn < 2 * l2 + 1; nn++) {
                    double u2r, u2i; h_umat_entry(l2, bb, nn, &u2r, &u2i); u2i = -u2i;
                    if (u2r == 0.0 && u2i == 0.0) continue;
                    double pr = u1r * u2r - u1i * u2i;
                    double pi = u1r * u2i + u1i * u2r;
                    for (int o = 0; o < 2 * l3 + 1; o++) {
                        double u3r, u3i; h_umat_entry(l3, cc, o, &u3r, &u3i);
                        if (u3r == 0.0 && u3i == 0.0) continue;
                        double C = h_cg_complex(l1, m - l1, l2, nn - l2, l3, o - l3);
                        if (C == 0.0) continue;
                        re += (pr * u3r - pi * u3i) * C;
                        im += (pr * u3i + pi * u3r) * C;
                    }
                }
            }
        }
        double val = ((l1 + l2 + l3) & 1) ? im : re;
        cg[t] = (float)val;
    }
}

// ================= DEVICE: prelude — warp-per-output dot products (~1.5us) =================
__device__ __forceinline__ float dot4(float4 v, float4 w) {
    return fmaf(v.x, w.x, fmaf(v.y, w.y, fmaf(v.z, w.z, v.w * w.w)));
}

__global__ void k_prep(const float* __restrict__ W3, const float* __restrict__ b3,
                       const float* __restrict__ Wt1, const float* __restrict__ bt1,
                       const float* __restrict__ Wt2, const float* __restrict__ bt2,
                       const float* __restrict__ wpath, PrepConst pc) {
    int tid = threadIdx.x;
    int warp = tid >> 5, lane = tid & 31;

    if (blockIdx.x < 96) {
        if (blockIdx.x == 0 && tid == 0) g_tile = 0;   // reset work-stealing counter
        int t = blockIdx.x * 8 + warp;
        int pl = t >> 7;
        const float4* w3r = reinterpret_cast<const float4*>(W3) + (size_t)t * 32;
        const float4* v1r = reinterpret_cast<const float4*>(Wt1) + pl * 32;
        const float4* v2r = reinterpret_cast<const float4*>(Wt2) + pl * 32;
        float4 w = w3r[lane];
        float a1 = dot4(w, v1r[lane]);
        float a2 = dot4(w, v2r[lane]);
        #pragma unroll
        for (int d = 16; d > 0; d >>= 1) {
            a1 += __shfl_xor_sync(0xffffffffu, a1, d);
            a2 += __shfl_xor_sync(0xffffffffu, a2, d);
        }
        if (lane == 0) { g_w1[t] = a1; g_w2[t] = a2; }
    } else {
        if (warp == 0) {
            const float4* br  = reinterpret_cast<const float4*>(b3);
            const float4* v1r = reinterpret_cast<const float4*>(Wt1);
            const float4* v2r = reinterpret_cast<const float4*>(Wt2);
            float4 b = br[lane];
            float a1 = dot4(b, v1r[lane]);
            float a2 = dot4(b, v2r[lane]);
            #pragma unroll
            for (int d = 16; d > 0; d >>= 1) {
                a1 += __shfl_xor_sync(0xffffffffu, a1, d);
                a2 += __shfl_xor_sync(0xffffffffu, a2, d);
            }
            if (lane == 0) { g_c1 = a1 + bt1[0]; g_c2 = a2 + bt2[0]; }
        } else {
            for (int i = tid - 32; i < 9 * MAXE; i += 224)
                g_lval[i] = pc.cgv[i] * wpath[pc.wpidx[i]];
        }
    }
}

// ================= DEVICE: main streaming kernel — cp.async warp pipeline =================
// One block/SM (smem-bound). Each warp independently steals one n at a time, keeps a
// private double buffer (2 x 9216B) filled via cp.async.cg (no register cost), and
// computes from smem: lanes 0-15 accumulate x1 dots (w1), lanes 16-31 x2 dots (w2).

__device__ __forceinline__ unsigned smem_u32(const void* p) {
    unsigned u;
    asm("{ .reg .u64 t; cvta.to.shared.u64 t, %1; cvt.u32.u64 %0, t; }" : "=r"(u) : "l"(p));
    return u;
}

__device__ __forceinline__ void cp16(unsigned dst, const void* src) {
    asm volatile("cp.async.cg.shared.global [%0], [%1], 16;" :: "r"(dst), "l"(src));
}
#define CP_COMMIT() asm volatile("cp.async.commit_group;" ::: "memory")
#define CP_WAIT1()  asm volatile("cp.async.wait_group 1;" ::: "memory")

__device__ __forceinline__ unsigned warp_grab() {
    unsigned t = 0;
    if ((threadIdx.x & 31) == 0) t = atomicAdd(&g_tile, 1u);
    return __shfl_sync(0xffffffffu, t, 0);
}

__global__ void __launch_bounds__(256, 1)
k_main(const float* __restrict__ sf, float* __restrict__ out, int N, MainConst mc) {
    extern __shared__ char smem_raw[];
    float* data   = (float*)smem_raw;                 // 8 warps * 2 bufs * 2304 floats
    float* w1s    = data + 8 * 4608;                  // 768
    float* w2s    = w1s + 768;                        // 768
    float* lval_s = w2s + 768;                        // 432
    float* cgos   = lval_s + 9 * MAXE;                // 81
    float* xbufs  = cgos + 81;                        // 8 * 36
    float* tpbufs = xbufs + 8 * 36;                   // 8 * 9
    int*   lcnt_s = (int*)(tpbufs + 8 * 9);           // 9
    unsigned char* lab_s = (unsigned char*)(lcnt_s + 9);  // 432

    int tid = threadIdx.x;
    for (int i = tid; i < 768; i += 256) { w1s[i] = g_w1[i]; w2s[i] = g_w2[i]; }
    for (int i = tid; i < 9 * MAXE; i += 256) { lval_s[i] = g_lval[i]; lab_s[i] = mc.lab[i]; }
    if (tid < 81) cgos[tid] = mc.cgos[tid];
    if (tid < 9)  lcnt_s[tid] = mc.lcnt[tid];
    float c1 = g_c1, c2 = g_c2;
    __syncthreads();

    int warp = tid >> 5, lane = tid & 31;
    int h = lane >> 4;                  // 0: x1/w1 half, 1: x2/w2 half
    int q = lane & 15;                  // column pair {q, q+16}

    float* buf0 = data + warp * 4608;           // parity-0 buffer (2304 floats)
    float* buf1 = buf0 + 2304;                  // parity-1 buffer
    unsigned d0 = smem_u32(buf0) + lane * 16;
    unsigned d1 = smem_u32(buf1) + lane * 16;
    const char* sfc = (const char*)sf;

    float* xbuf  = xbufs  + warp * 36;
    float* tpbuf = tpbufs + warp * 9;

    unsigned uN = (unsigned)N;

    // ---- pipeline prologue: grab 2 n's, start both loads ----
    unsigned n0 = warp_grab();
    if (n0 < uN) {
        const char* src = sfc + (size_t)n0 * 9216 + lane * 16;
        #pragma unroll
        for (int k = 0; k < 18; k++) cp16(d0 + k * 512, src + k * 512);
    }
    CP_COMMIT();
    unsigned n1 = warp_grab();
    if (n1 < uN) {
        const char* src = sfc + (size_t)n1 * 9216 + lane * 16;
        #pragma unroll
        for (int k = 0; k < 18; k++) cp16(d1 + k * 512, src + k * 512);
    }
    CP_COMMIT();

    int pb = 0;
    while (n0 < uN) {
        unsigned n2 = warp_grab();              // steal next-next (latency hidden)

        CP_WAIT1();                             // n0's data resident
        __syncwarp();

        float* buf = pb ? buf1 : buf0;
        const float* ws = h ? w2s : w1s;

        // ---- 18 per-row partial dots over columns {q, q+16} ----
        float s[18];
        {
            int r = 0;
            #pragma unroll
            for (int p = 0; p < 2; p++) {
                #pragma unroll
                for (int l = 0; l < 3; l++) {
                    const float4* wp = reinterpret_cast<const float4*>(ws) + (p * 3 + l) * 32;
                    float4 a0 = wp[q], a1 = wp[q + 16];
                    const int nlm = 2 * l + 1;
                    #pragma unroll
                    for (int j = 0; j < nlm; j++) {
                        const float4* rp = reinterpret_cast<const float4*>(buf) + (p * 9 + l * l + j) * 32;
                        s[r] = dot4(rp[q], a0) + dot4(rp[q + 16], a1);
                        r++;
                    }
                }
            }
        }
        // ---- width-16 butterfly within each half-warp ----
        #pragma unroll
        for (int r = 0; r < 18; r++) {
            s[r] += __shfl_xor_sync(0xffffffffu, s[r], 1);
            s[r] += __shfl_xor_sync(0xffffffffu, s[r], 2);
            s[r] += __shfl_xor_sync(0xffffffffu, s[r], 4);
            s[r] += __shfl_xor_sync(0xffffffffu, s[r], 8);
        }
        s[0] += h ? c2 : c1;                    // bias on even-parity scalar channel

        if (q == 0) {                           // lane 0 -> x1, lane 16 -> x2
            #pragma unroll
            for (int r = 0; r < 18; r++) xbuf[h * 18 + r] = s[r];
        }
        __syncwarp();

        // ---- sparse tensor product tp[c] (lanes 0-8) ----
        if (lane < 9) {
            int c = lane;
            float tp = 0.f;
            int cnt = lcnt_s[c];
            const unsigned char* pab = lab_s + c * MAXE;
            const float*         pv  = lval_s + c * MAXE;
            for (int e = 0; e < cnt; e++) {
                int ab = pab[e];
                float val = pv[e];
                int a = ab >> 4, b = ab & 15;
                float t0 = xbuf[a] * xbuf[18 + b];
                float t1 = fmaf(xbuf[9 + a], xbuf[27 + b], t0);
                tp = fmaf(val, t1, tp);
            }
            tpbuf[c] = tp;
        }
        __syncwarp();

        // ---- out[i,j] = sum_c tp[c] * CG[1+i,1+j,c] (lanes 0-8) ----
        if (lane < 9) {
            int k = lane;
            float o = 0.f;
            #pragma unroll
            for (int c = 0; c < 9; c++) o = fmaf(tpbuf[c], cgos[k * 9 + c], o);
            out[(size_t)n0 * 9 + k] = o;
        }
        __syncwarp();                           // all lanes done with buf before refill

        // ---- refill consumed buffer with n2 ----
        if (n2 < uN) {
            const char* src = sfc + (size_t)n2 * 9216 + lane * 16;
            unsigned dst = pb ? d1 : d0;
            #pragma unroll
            for (int k = 0; k < 18; k++) cp16(dst + k * 512, src + k * 512);
        }
        CP_COMMIT();

        n0 = n1; n1 = n2; pb ^= 1;
    }
}

// ================= launch =================
extern "C" void kernel_launch(void* const* d_in, const int* in_sizes, int n_in,
                              void* d_out, int out_size) {
    const float* sf    = (const float*)d_in[0];
    const float* W3    = (const float*)d_in[1];
    const float* b3    = (const float*)d_in[2];
    const float* Wt1   = (const float*)d_in[3];
    const float* bt1   = (const float*)d_in[4];
    const float* Wt2   = (const float*)d_in[5];
    const float* bt2   = (const float*)d_in[6];
    const float* wpath = (const float*)d_in[7];

    int N = in_sizes[0] / 2304;  // N * 2 * 9 * 128

    // ---- host-side constant construction (pure CPU, graph-safe) ----
    float cg[729];
    h_build_cg(cg);

    PrepConst pc;
    MainConst mcst;
    memset(&pc, 0, sizeof(pc));
    memset(&mcst, 0, sizeof(mcst));

    for (int t = 0; t < 81; t++) {
        int k = t / 9, c = t % 9;
        int ii = k / 3, jj = k % 3;
        mcst.cgos[t] = cg[(1 + ii) * 81 + (1 + jj) * 9 + c];
    }
    for (int c = 0; c < 9; c++) {
        int cnt = 0;
        for (int ab = 0; ab < 81; ab++) {
            int idx = ab * 9 + c;
            if (fabsf(cg[idx]) > 1e-6f && cnt < MAXE) {
                int a = ab / 9, b = ab % 9;
                mcst.lab[c * MAXE + cnt] = (unsigned char)((a << 4) | b);
                pc.cgv[c * MAXE + cnt]   = cg[idx];
                pc.wpidx[c * MAXE + cnt] = (unsigned char)((h_lof(a) * 3 + h_lof(b)) * 3 + h_lof(c));
                cnt++;
            }
        }
        mcst.lcnt[c] = cnt;
    }

    // dynamic smem: 8*4608 + 768 + 768 + 432 + 81 + 288 + 72 floats + lcnt/lab bytes
    const int SMEM_BYTES = (8 * 4608 + 768 + 768 + 9 * MAXE + 81 + 8 * 36 + 8 * 9) * 4
                           + 9 * 4 + 9 * MAXE + 128;
    static int smem_set = 0;
    if (!smem_set) {
        cudaFuncSetAttribute(k_main, cudaFuncAttributeMaxDynamicSharedMemorySize, SMEM_BYTES);
        smem_set = 1;
    }

    // ---- device work: parallel prelude (+counter reset) + warp-pipelined streaming ----
    k_prep<<<97, 256>>>(W3, b3, Wt1, bt1, Wt2, bt2, wpath, pc);
    k_main<<<160, 256, SMEM_BYTES>>>(sf, (float*)d_out, N, mcst);
}

// round 17
// speedup vs baseline: 1.0045x; 1.0002x over previous
#include <cuda_runtime.h>
#include <math.h>
#include <string.h>

#define MAXE 48

// ---------------- device-global scratch (weight/wpath-dependent only) ----------------
__device__ float g_w1[768];          // pre-contracted W3@Wt1 : [p][l][128]
__device__ float g_w2[768];          // pre-contracted W3@Wt2
__device__ float g_c1, g_c2;         // bias scalars for (p=0, lm=0)
__device__ float g_lval[9 * MAXE];   // CG * wpath, per-c sparse lists
__device__ unsigned g_tile;          // work-stealing counter (reset each launch in k_prep)

// ---------------- host-computed constants passed by value (constant bank) ----------------
struct PrepConst {
    float         cgv[9 * MAXE];     // CG value per sparse entry (0 in unused slots)
    unsigned char wpidx[9 * MAXE];   // wpath flat index per sparse entry
};
struct MainConst {
    float         cgos[81];          // CG[1+i][1+j][c] laid out [k=i*3+j][c]
    int           lcnt[9];           // sparse-list counts per output c
    unsigned char lab[9 * MAXE];     // packed (a<<4)|b per sparse entry
};

// ================= HOST: Clebsch-Gordan construction (double precision) =================
static inline int h_lof(int i) { return i >= 4 ? 2 : (i >= 1 ? 1 : 0); }

static double h_dfact(int n) {
    static const double F[8] = {1., 1., 2., 6., 24., 120., 720., 5040.};
    return F[n];
}

static double h_cg_complex(int j1, int m1, int j2, int m2, int j3, int m3) {
    if (m3 != m1 + m2) return 0.0;
    int lo = j1 - j2; if (lo < 0) lo = -lo;
    if (j3 < lo || j3 > j1 + j2) return 0.0;
    double pref = sqrt((2.0 * j3 + 1.0) * h_dfact(j1 + j2 - j3) * h_dfact(j1 - j2 + j3) *
                       h_dfact(-j1 + j2 + j3) / h_dfact(j1 + j2 + j3 + 1));
    pref *= sqrt(h_dfact(j1 + m1) * h_dfact(j1 - m1) * h_dfact(j2 + m2) * h_dfact(j2 - m2) *
                 h_dfact(j3 + m3) * h_dfact(j3 - m3));
    double s = 0.0;
    for (int k = 0; k <= j1 + j2 - j3; k++) {
        int t1 = j1 + j2 - j3 - k, t2 = j1 - m1 - k, t3 = j2 + m2 - k;
        int t4 = j3 - j2 + m1 + k, t5 = j3 - j1 - m2 + k;
        if (t1 < 0 || t2 < 0 || t3 < 0 || t4 < 0 || t5 < 0) continue;
        double d = h_dfact(k) * h_dfact(t1) * h_dfact(t2) * h_dfact(t3) * h_dfact(t4) * h_dfact(t5);
        s += ((k & 1) ? -1.0 : 1.0) / d;
    }
    return pref * s;
}

static void h_umat_entry(int l, int r, int c, double* re, double* im) {
    *re = 0.0; *im = 0.0;
    int mr = r - l, mc = c - l;
    const double inv = 0.70710678118654752440;
    if (mr == 0) { if (mc == 0) *re = 1.0; return; }
    if (mr > 0) {
        int m = mr; double sgn = (m & 1) ? -1.0 : 1.0;
        if (mc == -m) *re = inv;
        else if (mc == m) *re = sgn * inv;
    } else {
        int m = -mr; double sgn = (m & 1) ? -1.0 : 1.0;
        if (mc == -m) *im = inv;
        else if (mc == m) *im = -sgn * inv;
    }
}

static void h_build_cg(float* cg /*729*/) {
    for (int t = 0; t < 729; t++) {
        int a = t / 81, b = (t / 9) % 9, c = t % 9;
        int l1 = h_lof(a), l2 = h_lof(b), l3 = h_lof(c);
        double re = 0.0, im = 0.0;
        int lo = l1 - l2; if (lo < 0) lo = -lo;
        if (l3 >= lo && l3 <= l1 + l2) {
            int aa = a - l1 * l1, bb = b - l2 * l2, cc = c - l3 * l3;
            for (int m = 0; m < 2 * l1 + 1; m++) {
                double u1r, u1i; h_umat_entry(l1, aa, m, &u1r, &u1i); u1i = -u1i;
                if (u1r == 0.0 && u1i == 0.0) continue;
                for (int nn = 0; nn < 2 * l2 + 1; nn++) {
                    double u2r, u2i; h_umat_entry(l2, bb, nn, &u2r, &u2i); u2i = -u2i;
                    if (u2r == 0.0 && u2i == 0.0) continue;
                    double pr = u1r * u2r - u1i * u2i;
                    double pi = u1r * u2i + u1i * u2r;
                    for (int o = 0; o < 2 * l3 + 1; o++) {
                        double u3r, u3i; h_umat_entry(l3, cc, o, &u3r, &u3i);
                        if (u3r == 0.0 && u3i == 0.0) continue;
                        double C = h_cg_complex(l1, m - l1, l2, nn - l2, l3, o - l3);
                        if (C == 0.0) continue;
                        re += (pr * u3r - pi * u3i) * C;
                        im += (pr * u3i + pi * u3r) * C;
                    }
                }
            }
        }
        double val = ((l1 + l2 + l3) & 1) ? im : re;
        cg[t] = (float)val;
    }
}

// ================= DEVICE: prelude — warp-per-output dot products (~1.5us) =================
__device__ __forceinline__ float dot4(float4 v, float4 w) {
    return fmaf(v.x, w.x, fmaf(v.y, w.y, fmaf(v.z, w.z, v.w * w.w)));
}

__global__ void k_prep(const float* __restrict__ W3, const float* __restrict__ b3,
                       const float* __restrict__ Wt1, const float* __restrict__ bt1,
                       const float* __restrict__ Wt2, const float* __restrict__ bt2,
                       const float* __restrict__ wpath, PrepConst pc) {
    int tid = threadIdx.x;
    int warp = tid >> 5, lane = tid & 31;

    if (blockIdx.x < 96) {
        if (blockIdx.x == 0 && tid == 0) g_tile = 0;   // reset work-stealing counter
        int t = blockIdx.x * 8 + warp;
        int pl = t >> 7;
        const float4* w3r = reinterpret_cast<const float4*>(W3) + (size_t)t * 32;
        const float4* v1r = reinterpret_cast<const float4*>(Wt1) + pl * 32;
        const float4* v2r = reinterpret_cast<const float4*>(Wt2) + pl * 32;
        float4 w = w3r[lane];
        float a1 = dot4(w, v1r[lane]);
        float a2 = dot4(w, v2r[lane]);
        #pragma unroll
        for (int d = 16; d > 0; d >>= 1) {
            a1 += __shfl_xor_sync(0xffffffffu, a1, d);
            a2 += __shfl_xor_sync(0xffffffffu, a2, d);
        }
        if (lane == 0) { g_w1[t] = a1; g_w2[t] = a2; }
    } else {
        if (warp == 0) {
            const float4* br  = reinterpret_cast<const float4*>(b3);
            const float4* v1r = reinterpret_cast<const float4*>(Wt1);
            const float4* v2r = reinterpret_cast<const float4*>(Wt2);
            float4 b = br[lane];
            float a1 = dot4(b, v1r[lane]);
            float a2 = dot4(b, v2r[lane]);
            #pragma unroll
            for (int d = 16; d > 0; d >>= 1) {
                a1 += __shfl_xor_sync(0xffffffffu, a1, d);
                a2 += __shfl_xor_sync(0xffffffffu, a2, d);
            }
            if (lane == 0) { g_c1 = a1 + bt1[0]; g_c2 = a2 + bt2[0]; }
        } else {
            for (int i = tid - 32; i < 9 * MAXE; i += 224)
                g_lval[i] = pc.cgv[i] * wpath[pc.wpidx[i]];
        }
    }
}

// ================= DEVICE: main streaming kernel — cp.async warp pipeline =================
// One block/SM (smem-bound). Each warp independently steals one n at a time, keeps a
// private double buffer (2 x 9216B) filled via cp.async.cg (no register cost), and
// computes from smem: lanes 0-15 accumulate x1 dots (w1), lanes 16-31 x2 dots (w2).

__device__ __forceinline__ unsigned smem_u32(const void* p) {
    unsigned u;
    asm("{ .reg .u64 t; cvta.to.shared.u64 t, %1; cvt.u32.u64 %0, t; }" : "=r"(u) : "l"(p));
    return u;
}

__device__ __forceinline__ void cp16(unsigned dst, const void* src) {
    asm volatile("cp.async.cg.shared.global [%0], [%1], 16;" :: "r"(dst), "l"(src));
}
#define CP_COMMIT() asm volatile("cp.async.commit_group;" ::: "memory")
#define CP_WAIT1()  asm volatile("cp.async.wait_group 1;" ::: "memory")

__device__ __forceinline__ unsigned warp_grab() {
    unsigned t = 0;
    if ((threadIdx.x & 31) == 0) t = atomicAdd(&g_tile, 1u);
    return __shfl_sync(0xffffffffu, t, 0);
}

__global__ void __launch_bounds__(256, 1)
k_main(const float* __restrict__ sf, float* __restrict__ out, int N, MainConst mc) {
    extern __shared__ char smem_raw[];
    float* data   = (float*)smem_raw;                 // 8 warps * 2 bufs * 2304 floats
    float* w1s    = data + 8 * 4608;                  // 768
    float* w2s    = w1s + 768;                        // 768
    float* lval_s = w2s + 768;                        // 432
    float* cgos   = lval_s + 9 * MAXE;                // 81
    float* xbufs  = cgos + 81;                        // 8 * 36
    float* tpbufs = xbufs + 8 * 36;                   // 8 * 9
    int*   lcnt_s = (int*)(tpbufs + 8 * 9);           // 9
    unsigned char* lab_s = (unsigned char*)(lcnt_s + 9);  // 432

    int tid = threadIdx.x;
    for (int i = tid; i < 768; i += 256) { w1s[i] = g_w1[i]; w2s[i] = g_w2[i]; }
    for (int i = tid; i < 9 * MAXE; i += 256) { lval_s[i] = g_lval[i]; lab_s[i] = mc.lab[i]; }
    if (tid < 81) cgos[tid] = mc.cgos[tid];
    if (tid < 9)  lcnt_s[tid] = mc.lcnt[tid];
    float c1 = g_c1, c2 = g_c2;
    __syncthreads();

    int warp = tid >> 5, lane = tid & 31;
    int h = lane >> 4;                  // 0: x1/w1 half, 1: x2/w2 half
    int q = lane & 15;                  // column pair {q, q+16}

    float* buf0 = data + warp * 4608;           // parity-0 buffer (2304 floats)
    float* buf1 = buf0 + 2304;                  // parity-1 buffer
    unsigned d0 = smem_u32(buf0) + lane * 16;
    unsigned d1 = smem_u32(buf1) + lane * 16;
    const char* sfc = (const char*)sf;

    float* xbuf  = xbufs  + warp * 36;
    float* tpbuf = tpbufs + warp * 9;

    unsigned uN = (unsigned)N;

    // ---- pipeline prologue: grab 2 n's, start both loads ----
    unsigned n0 = warp_grab();
    if (n0 < uN) {
        const char* src = sfc + (size_t)n0 * 9216 + lane * 16;
        #pragma unroll
        for (int k = 0; k < 18; k++) cp16(d0 + k * 512, src + k * 512);
    }
    CP_COMMIT();
    unsigned n1 = warp_grab();
    if (n1 < uN) {
        const char* src = sfc + (size_t)n1 * 9216 + lane * 16;
        #pragma unroll
        for (int k = 0; k < 18; k++) cp16(d1 + k * 512, src + k * 512);
    }
    CP_COMMIT();

    int pb = 0;
    while (n0 < uN) {
        unsigned n2 = warp_grab();              // steal next-next (latency hidden)

        CP_WAIT1();                             // n0's data resident
        __syncwarp();

        float* buf = pb ? buf1 : buf0;
        const float* ws = h ? w2s : w1s;

        // ---- 18 per-row partial dots over columns {q, q+16} ----
        float s[18];
        {
            int r = 0;
            #pragma unroll
            for (int p = 0; p < 2; p++) {
                #pragma unroll
                for (int l = 0; l < 3; l++) {
                    const float4* wp = reinterpret_cast<const float4*>(ws) + (p * 3 + l) * 32;
                    float4 a0 = wp[q], a1 = wp[q + 16];
                    const int nlm = 2 * l + 1;
                    #pragma unroll
                    for (int j = 0; j < nlm; j++) {
                        const float4* rp = reinterpret_cast<const float4*>(buf) + (p * 9 + l * l + j) * 32;
                        s[r] = dot4(rp[q], a0) + dot4(rp[q + 16], a1);
                        r++;
                    }
                }
            }
        }
        // ---- width-16 butterfly within each half-warp ----
        #pragma unroll
        for (int r = 0; r < 18; r++) {
            s[r] += __shfl_xor_sync(0xffffffffu, s[r], 1);
            s[r] += __shfl_xor_sync(0xffffffffu, s[r], 2);
            s[r] += __shfl_xor_sync(0xffffffffu, s[r], 4);
            s[r] += __shfl_xor_sync(0xffffffffu, s[r], 8);
        }
        s[0] += h ? c2 : c1;                    // bias on even-parity scalar channel

        if (q == 0) {                           // lane 0 -> x1, lane 16 -> x2
            #pragma unroll
            for (int r = 0; r < 18; r++) xbuf[h * 18 + r] = s[r];
        }
        __syncwarp();

        // ---- sparse tensor product tp[c] (lanes 0-8) ----
        if (lane < 9) {
            int c = lane;
            float tp = 0.f;
            int cnt = lcnt_s[c];
            const unsigned char* pab = lab_s + c * MAXE;
            const float*         pv  = lval_s + c * MAXE;
            for (int e = 0; e < cnt; e++) {
                int ab = pab[e];
                float val = pv[e];
                int a = ab >> 4, b = ab & 15;
                float t0 = xbuf[a] * xbuf[18 + b];
                float t1 = fmaf(xbuf[9 + a], xbuf[27 + b], t0);
                tp = fmaf(val, t1, tp);
            }
            tpbuf[c] = tp;
        }
        __syncwarp();

        // ---- out[i,j] = sum_c tp[c] * CG[1+i,1+j,c] (lanes 0-8) ----
        if (lane < 9) {
            int k = lane;
            float o = 0.f;
            #pragma unroll
            for (int c = 0; c < 9; c++) o = fmaf(tpbuf[c], cgos[k * 9 + c], o);
            out[(size_t)n0 * 9 + k] = o;
        }
        __syncwarp();                           // all lanes done with buf before refill

        // ---- refill consumed buffer with n2 ----
        if (n2 < uN) {
            const char* src = sfc + (size_t)n2 * 9216 + lane * 16;
            unsigned dst = pb ? d1 : d0;
            #pragma unroll
            for (int k = 0; k < 18; k++) cp16(dst + k * 512, src + k * 512);
        }
        CP_COMMIT();

        n0 = n1; n1 = n2; pb ^= 1;
    }
}

// ================= launch =================
extern "C" void kernel_launch(void* const* d_in, const int* in_sizes, int n_in,
                              void* d_out, int out_size) {
    const float* sf    = (const float*)d_in[0];
    const float* W3    = (const float*)d_in[1];
    const float* b3    = (const float*)d_in[2];
    const float* Wt1   = (const float*)d_in[3];
    const float* bt1   = (const float*)d_in[4];
    const float* Wt2   = (const float*)d_in[5];
    const float* bt2   = (const float*)d_in[6];
    const float* wpath = (const float*)d_in[7];

    int N = in_sizes[0] / 2304;  // N * 2 * 9 * 128

    // ---- host-side constant construction (pure CPU, graph-safe) ----
    float cg[729];
    h_build_cg(cg);

    PrepConst pc;
    MainConst mcst;
    memset(&pc, 0, sizeof(pc));
    memset(&mcst, 0, sizeof(mcst));

    for (int t = 0; t < 81; t++) {
        int k = t / 9, c = t % 9;
        int ii = k / 3, jj = k % 3;
        mcst.cgos[t] = cg[(1 + ii) * 81 + (1 + jj) * 9 + c];
    }
    for (int c = 0; c < 9; c++) {
        int cnt = 0;
        for (int ab = 0; ab < 81; ab++) {
            int idx = ab * 9 + c;
            if (fabsf(cg[idx]) > 1e-6f && cnt < MAXE) {
                int a = ab / 9, b = ab % 9;
                mcst.lab[c * MAXE + cnt] = (unsigned char)((a << 4) | b);
                pc.cgv[c * MAXE + cnt]   = cg[idx];
                pc.wpidx[c * MAXE + cnt] = (unsigned char)((h_lof(a) * 3 + h_lof(b)) * 3 + h_lof(c));
                cnt++;
            }
        }
        mcst.lcnt[c] = cnt;
    }

    // dynamic smem: 8*4608 + 768 + 768 + 432 + 81 + 288 + 72 floats + lcnt/lab bytes
    const int SMEM_BYTES = (8 * 4608 + 768 + 768 + 9 * MAXE + 81 + 8 * 36 + 8 * 9) * 4
                           + 9 * 4 + 9 * MAXE + 128;
    static int smem_set = 0;
    if (!smem_set) {
        cudaFuncSetAttribute(k_main, cudaFuncAttributeMaxDynamicSharedMemorySize, SMEM_BYTES);
        smem_set = 1;
    }

    // ---- device work: parallel prelude (+counter reset) + warp-pipelined streaming ----
    k_prep<<<97, 256>>>(W3, b3, Wt1, bt1, Wt2, bt2, wpath, pc);
    k_main<<<160, 256, SMEM_BYTES>>>(sf, (float*)d_out, N, mcst);
}